// round 16
// baseline (speedup 1.0000x reference)
#include <cuda_runtime.h>
#include <cuda_fp16.h>
#include <cstdint>

#define NU 100000
#define NP 200000
#define H  128
#define EV 500000
#define EL 150000
#define NALL (2*NP + 2*NU)        // 600000
#define NE   (2*(EV + EL))        // 1300000 linked-list entries
#define GP 1563                   // ceil(NP/128)
#define GU 782                    // ceil(NU/128)

// ---------------- scratch layout (4-byte float units) ----------------
#define OFF_AGG 0LL               // agg slots contiguous: [VP|LP|VU|LU] x 128 fp16
#define OFF_XU0 38400000LL        // emb_u fp16
#define OFF_XP0 44800000LL        // emb_p fp16
#define OFF_XU1 57600000LL
#define OFF_XP1 64000000LL
#define OFF_INT 76800000LL
#define OFF_BH  80600000LL        // 4*49152 fp16
#define OFF_BIAS 80698304LL
#define SCRATCH_FLOATS 80700000LL

// int offsets inside int region (3.8M ints available)
#define I_HEAD 0                  // NALL heads
#define I_ENT  600064             // int2 x NE = 2.6M ints

__device__ __align__(1024) float g_scratch[SCRATCH_FLOATS];

// ---------------- PTX helpers (base-target safe, sm_80-class) ----------------
__device__ __forceinline__ uint32_t smem_u32(const void* p) {
    uint32_t a;
    asm("{ .reg .u64 t; cvta.to.shared.u64 t, %1; cvt.u32.u64 %0, t; }" : "=r"(a) : "l"(p));
    return a;
}
__device__ __forceinline__ void ldsm_x4(uint32_t& r0, uint32_t& r1, uint32_t& r2, uint32_t& r3,
                                        uint32_t addr) {
    asm volatile("ldmatrix.sync.aligned.m8n8.x4.shared.b16 {%0,%1,%2,%3}, [%4];"
                 : "=r"(r0), "=r"(r1), "=r"(r2), "=r"(r3) : "r"(addr));
}
__device__ __forceinline__ void mma_f16(float* d, const uint32_t* a, const uint32_t* b) {
    asm volatile("mma.sync.aligned.m16n8k16.row.col.f32.f16.f16.f32 "
                 "{%0,%1,%2,%3}, {%4,%5,%6,%7}, {%8,%9}, {%0,%1,%2,%3};"
                 : "+f"(d[0]), "+f"(d[1]), "+f"(d[2]), "+f"(d[3])
                 : "r"(a[0]), "r"(a[1]), "r"(a[2]), "r"(a[3]), "r"(b[0]), "r"(b[1]));
}
__device__ __forceinline__ void cp16(uint32_t dst, const void* src) {
    asm volatile("cp.async.cg.shared.global [%0], [%1], 16;"
                 :: "r"(dst), "l"(src) : "memory");
}
__device__ __forceinline__ void cp16z(uint32_t dst, const void* src, int sz) {
    asm volatile("cp.async.cg.shared.global [%0], [%1], 16, %2;"
                 :: "r"(dst), "l"(src), "r"(sz) : "memory");
}
#define CP_COMMIT() asm volatile("cp.async.commit_group;" ::: "memory")
#define CP_WAIT1()  asm volatile("cp.async.wait_group 1;" ::: "memory")
#define CP_WAIT0()  asm volatile("cp.async.wait_group 0;" ::: "memory")

// ---------------- prep: B fp16 + bias, emb cvt, head init ----------------
#define CVT_GROUPS ((NU + NP) * 16)
#define CVT_BLOCKS ((CVT_GROUPS + 255) / 256)  // 18750
#define HEAD_BLOCKS ((NALL + 1023) / 1024)     // 586 (4 ints/thread)
#define PREP_GRID (768 + CVT_BLOCKS + HEAD_BLOCKS)
__global__ void k_prep(const float* __restrict__ Wl, const float* __restrict__ bl,
                       const float* __restrict__ Wr,
                       const float* __restrict__ eu, const float* __restrict__ ep,
                       __half* __restrict__ Bh, float* __restrict__ Bias,
                       __half* __restrict__ xu16, __half* __restrict__ xp16,
                       int* __restrict__ head) {
    int b = blockIdx.x;
    if (b < 768) {
        int t = b / 192;
        int idx = (b % 192) * 256 + threadIdx.x;
        int layer = t >> 1, isU = t & 1;
        int rV = isU ? 1 : 0, rL = rV + 2;
        int n = idx / 384, k = idx % 384;
        const float* WlV = Wl + (size_t)((layer * 4 + rV) * 128) * 128;
        const float* WlL = Wl + (size_t)((layer * 4 + rL) * 128) * 128;
        const float* WrV = Wr + (size_t)((layer * 4 + rV) * 128) * 128;
        const float* WrL = Wr + (size_t)((layer * 4 + rL) * 128) * 128;
        float v;
        if (k < 128)      v = WlV[n * 128 + k];
        else if (k < 256) v = WlL[n * 128 + (k - 128)];
        else              v = WrV[n * 128 + (k - 256)] + WrL[n * 128 + (k - 256)];
        Bh[(size_t)t * 49152 + idx] = __float2half_rn(v);
        if (idx < 128)
            Bias[t * 128 + idx] = bl[(layer * 4 + rV) * 128 + idx] + bl[(layer * 4 + rL) * 128 + idx];
    } else if (b < 768 + CVT_BLOCKS) {
        long i = (long)(b - 768) * 256 + threadIdx.x;
        if (i >= CVT_GROUPS) return;
        const float* src; __half* dst; long j;
        if (i < (long)NU * 16) { src = eu; dst = xu16; j = i; }
        else                   { src = ep; dst = xp16; j = i - (long)NU * 16; }
        float4 a = __ldg(reinterpret_cast<const float4*>(src) + j * 2);
        float4 c = __ldg(reinterpret_cast<const float4*>(src) + j * 2 + 1);
        __half2 h0 = __floats2half2_rn(a.x, a.y);
        __half2 h1 = __floats2half2_rn(a.z, a.w);
        __half2 h2 = __floats2half2_rn(c.x, c.y);
        __half2 h3 = __floats2half2_rn(c.z, c.w);
        uint4 o;
        o.x = *reinterpret_cast<uint32_t*>(&h0);
        o.y = *reinterpret_cast<uint32_t*>(&h1);
        o.z = *reinterpret_cast<uint32_t*>(&h2);
        o.w = *reinterpret_cast<uint32_t*>(&h3);
        reinterpret_cast<uint4*>(dst)[j] = o;
    } else {
        long i = (long)(b - 768 - CVT_BLOCKS) * 1024 + threadIdx.x * 4;
        if (i + 3 < NALL)
            *reinterpret_cast<int4*>(head + i) = make_int4(-1, -1, -1, -1);
        else
            for (long q = i; q < NALL; ++q) head[q] = -1;
    }
}

// ---------------- single-pass linked-list CSR build ----------------
__global__ void k_scatter_ll(const int* __restrict__ vs, const int* __restrict__ vd,
                             const int* __restrict__ ls, const int* __restrict__ ld,
                             int* __restrict__ head, int2* __restrict__ ent) {
    int i = blockIdx.x * blockDim.x + threadIdx.x;
    if (i < EV) {
        int s = vs[i], d = vd[i];
        int e0 = i;
        int p0 = atomicExch(&head[d], e0);
        ent[e0] = make_int2(s, p0);
        int e1 = EV + i;
        int p1 = atomicExch(&head[2 * NP + s], e1);
        ent[e1] = make_int2(d, p1);
    }
    if (i < EL) {
        int s = ls[i], d = ld[i];
        int e2 = 2 * EV + i;
        int p2 = atomicExch(&head[NP + d], e2);
        ent[e2] = make_int2(s, p2);
        int e3 = 2 * EV + EL + i;
        int p3 = atomicExch(&head[2 * NP + NU + s], e3);
        ent[e3] = make_int2(d, p3);
    }
}

// ---------------- linked-list mean aggregation: 2 nodes per warp ----------------
__global__ void agg_ll2(const int* __restrict__ head, const int2* __restrict__ ent,
                        const __half* __restrict__ xu, const __half* __restrict__ xp,
                        __half* __restrict__ aggAll) {
    int warpid = (blockIdx.x * blockDim.x + threadIdx.x) >> 5;
    int lane = threadIdx.x & 31;
    int half = lane >> 4;
    int l16 = lane & 15;
    int w = 2 * warpid + half;
    if (w >= NALL) return;
    const __half* X = (w < 2 * NP) ? xu : xp;
    int e = __ldg(head + w);
    float2 sa0 = make_float2(0.f, 0.f), sa1 = make_float2(0.f, 0.f);
    float2 sa2 = make_float2(0.f, 0.f), sa3 = make_float2(0.f, 0.f);
    int deg = 0;
    while (e >= 0) {
        int2 t = __ldg(ent + e);
        uint4 v = __ldg(reinterpret_cast<const uint4*>(X + (size_t)t.x * H) + l16);
        float2 f;
        f = __half22float2(*reinterpret_cast<__half2*>(&v.x)); sa0.x += f.x; sa0.y += f.y;
        f = __half22float2(*reinterpret_cast<__half2*>(&v.y)); sa1.x += f.x; sa1.y += f.y;
        f = __half22float2(*reinterpret_cast<__half2*>(&v.z)); sa2.x += f.x; sa2.y += f.y;
        f = __half22float2(*reinterpret_cast<__half2*>(&v.w)); sa3.x += f.x; sa3.y += f.y;
        ++deg;
        e = t.y;
    }
    float inv = 1.0f / fmaxf((float)deg, 1.0f);
    __half2 h0 = __floats2half2_rn(sa0.x * inv, sa0.y * inv);
    __half2 h1 = __floats2half2_rn(sa1.x * inv, sa1.y * inv);
    __half2 h2 = __floats2half2_rn(sa2.x * inv, sa2.y * inv);
    __half2 h3 = __floats2half2_rn(sa3.x * inv, sa3.y * inv);
    uint4 o;
    o.x = *reinterpret_cast<uint32_t*>(&h0);
    o.y = *reinterpret_cast<uint32_t*>(&h1);
    o.z = *reinterpret_cast<uint32_t*>(&h2);
    o.w = *reinterpret_cast<uint32_t*>(&h3);
    reinterpret_cast<uint4*>(aggAll + (size_t)w * H)[l16] = o;
}

// ---------------- merged dual-type GEMM: 3-stage cp.async, 1 barrier/chunk ----------------
// blocks [0,GU): users (reversed); [GU,GU+GP): posts (reversed) — L2 reuse of fresh agg writes.
#define RSTR 72
#define CHUNKB (128 * RSTR * 2)
#define GSMEM (6 * CHUNKB)            // 110592 B (3 A + 3 B buffers)

template <bool OUTH>
__global__ void __launch_bounds__(256, 2)
gemm_dual(const __half* __restrict__ pA0, const __half* __restrict__ pA1,
          const __half* __restrict__ pA2,
          const __half* __restrict__ uA0, const __half* __restrict__ uA1,
          const __half* __restrict__ uA2,
          const __half* __restrict__ BhP, const __half* __restrict__ BhU,
          const float* __restrict__ biasP, const float* __restrict__ biasU,
          void* __restrict__ outPv, void* __restrict__ outUv) {
    extern __shared__ __align__(16) __half sm[];
    const uint32_t sbase = smem_u32(sm);
    const uint32_t uAb[3] = {sbase, sbase + CHUNKB, sbase + 2 * CHUNKB};
    const uint32_t uBb[3] = {sbase + 3 * CHUNKB, sbase + 4 * CHUNKB, sbase + 5 * CHUNKB};

    const bool isU = blockIdx.x < GU;
    const int bidLoc = isU ? (GU - 1 - blockIdx.x) : (GP - 1 - (blockIdx.x - GU));
    const int row0 = bidLoc << 7;
    const int M = isU ? NU : NP;
    const __half* A0 = isU ? uA0 : pA0;
    const __half* A1 = isU ? uA1 : pA1;
    const __half* A2 = isU ? uA2 : pA2;
    const __half* Bh = isU ? BhU : BhP;
    const float* bias = isU ? biasU : biasP;
    void* outv = isU ? outUv : outPv;

    const int tid = threadIdx.x;
    const int warp = tid >> 5, lane = tid & 31;
    const int wm = warp & 3, wn = warp >> 2;

    float acc[2][8][4];
#pragma unroll
    for (int i = 0; i < 2; ++i)
#pragma unroll
        for (int j = 0; j < 8; ++j)
#pragma unroll
            for (int q = 0; q < 4; ++q) acc[i][j][q] = 0.f;

    const int sr = tid >> 1;
    const int shf = (tid & 1) << 5;
    const uint32_t soffB = (uint32_t)(sr * RSTR + shf) * 2;
    const int arow = row0 + sr;
    const int asz = (arow < M) ? 16 : 0;
    const int arowc = (arow < M) ? arow : row0;

    const int lA_row = lane & 15, lA_k = (lane >> 4) << 3;
    const int lB_row = ((lane >> 4) & 1) * 8 + (lane & 7);
    const int lB_k = ((lane >> 3) & 1) << 3;

    auto stage = [&](int c, int bi) {
        const __half* Asrc = (c < 2) ? A0 : (c < 4) ? A1 : A2;
        const int kb = (c & 1) << 6;
        const __half* ap = Asrc + (size_t)arowc * H + kb + shf;
        const __half* bp = Bh + (size_t)sr * 384 + c * 64 + shf;
#pragma unroll
        for (int q = 0; q < 4; ++q)
            cp16z(uAb[bi] + soffB + q * 16, ap + q * 8, asz);
#pragma unroll
        for (int q = 0; q < 4; ++q)
            cp16(uBb[bi] + soffB + q * 16, bp + q * 8);
    };

    stage(0, 0); CP_COMMIT();
    stage(1, 1); CP_COMMIT();

#pragma unroll 1
    for (int c = 0; c < 6; ++c) {
        const int bi = c % 3;
        if (c < 5) CP_WAIT1(); else CP_WAIT0();   // chunk c complete
        __syncthreads();                          // data visible + old buffer free
        if (c < 4) { stage(c + 2, (c + 2) % 3); CP_COMMIT(); }

#pragma unroll
        for (int ks = 0; ks < 4; ++ks) {
            uint32_t af[2][4];
#pragma unroll
            for (int mt = 0; mt < 2; ++mt) {
                uint32_t eo = ((wm * 32 + mt * 16 + lA_row) * RSTR + ks * 16 + lA_k) * 2;
                ldsm_x4(af[mt][0], af[mt][1], af[mt][2], af[mt][3], uAb[bi] + eo);
            }
            uint32_t bf[4][4];
#pragma unroll
            for (int np = 0; np < 4; ++np) {
                uint32_t eo = ((wn * 64 + np * 16 + lB_row) * RSTR + ks * 16 + lB_k) * 2;
                ldsm_x4(bf[np][0], bf[np][1], bf[np][2], bf[np][3], uBb[bi] + eo);
            }
#pragma unroll
            for (int mt = 0; mt < 2; ++mt)
#pragma unroll
                for (int nt = 0; nt < 8; ++nt)
                    mma_f16(acc[mt][nt], af[mt], &bf[nt >> 1][(nt & 1) << 1]);
        }
    }

    const int lr = lane >> 2;
    const int lc = (lane & 3) << 1;
#pragma unroll
    for (int mt = 0; mt < 2; ++mt) {
        int r0 = row0 + wm * 32 + mt * 16 + lr;
#pragma unroll
        for (int nt = 0; nt < 8; ++nt) {
            int cn = wn * 64 + nt * 8 + lc;
            float b0 = __ldg(bias + cn), b1 = __ldg(bias + cn + 1);
            float* a4 = acc[mt][nt];
            if (OUTH) {
                __half* o16 = (__half*)outv;
                if (r0 < M) {
                    __half2 h = __floats2half2_rn(fmaxf(a4[0] + b0, 0.f), fmaxf(a4[1] + b1, 0.f));
                    *reinterpret_cast<__half2*>(o16 + (size_t)r0 * H + cn) = h;
                }
                if (r0 + 8 < M) {
                    __half2 h = __floats2half2_rn(fmaxf(a4[2] + b0, 0.f), fmaxf(a4[3] + b1, 0.f));
                    *reinterpret_cast<__half2*>(o16 + (size_t)(r0 + 8) * H + cn) = h;
                }
            } else {
                float* o32 = (float*)outv;
                if (r0 < M)
                    *reinterpret_cast<float2*>(o32 + (size_t)r0 * H + cn) =
                        make_float2(a4[0] + b0, a4[1] + b1);
                if (r0 + 8 < M)
                    *reinterpret_cast<float2*>(o32 + (size_t)(r0 + 8) * H + cn) =
                        make_float2(a4[2] + b0, a4[3] + b1);
            }
        }
    }
}

// ---------------- host ----------------
extern "C" void kernel_launch(void* const* d_in, const int* in_sizes, int n_in,
                              void* d_out, int out_size) {
    (void)in_sizes; (void)n_in; (void)out_size;
    const float* emb_u = (const float*)d_in[0];
    const float* emb_p = (const float*)d_in[1];
    const float* W_l   = (const float*)d_in[2];
    const float* b_l   = (const float*)d_in[3];
    const float* W_r   = (const float*)d_in[4];
    const int*   ev_s  = (const int*)d_in[5];
    const int*   ev_d  = (const int*)d_in[6];
    const int*   el_s  = (const int*)d_in[7];
    const int*   el_d  = (const int*)d_in[8];

    float* base = 0;
    cudaGetSymbolAddress((void**)&base, g_scratch);

    __half* aggAll = (__half*)(base + OFF_AGG);
    __half* aVP = aggAll;
    __half* aLP = aggAll + (size_t)NP * H;
    __half* aVU = aggAll + (size_t)2 * NP * H;
    __half* aLU = aggAll + (size_t)(2 * NP + NU) * H;
    __half* xu0  = (__half*)(base + OFF_XU0);
    __half* xp0  = (__half*)(base + OFF_XP0);
    __half* xu1  = (__half*)(base + OFF_XU1);
    __half* xp1  = (__half*)(base + OFF_XP1);
    int*  ip   = (int*)(base + OFF_INT);
    int*  head = ip + I_HEAD;
    int2* ent  = (int2*)(ip + I_ENT);
    __half* Bh = (__half*)(base + OFF_BH);
    float* Bias = base + OFF_BIAS;

    float* outU = (float*)d_out;
    float* outP = outU + (size_t)NU * H;

    cudaFuncSetAttribute(gemm_dual<true>,  cudaFuncAttributeMaxDynamicSharedMemorySize, GSMEM);
    cudaFuncSetAttribute(gemm_dual<false>, cudaFuncAttributeMaxDynamicSharedMemorySize, GSMEM);

    // launches: prep(1), scatter_ll(2), agg(3), gemm<true>(4) <- profiled, agg(5), gemm(6)
    k_prep<<<PREP_GRID, 256>>>(W_l, b_l, W_r, emb_u, emb_p, Bh, Bias, xu0, xp0, head);
    k_scatter_ll<<<(EV + 255) / 256, 256>>>(ev_s, ev_d, el_s, el_d, head, ent);

    const int AGG_BLOCKS = (NALL / 2 + 7) / 8;

    agg_ll2<<<AGG_BLOCKS, 256>>>(head, ent, xu0, xp0, aggAll);
    gemm_dual<true><<<GP + GU, 256, GSMEM>>>(aVP, aLP, xp0, aVU, aLU, xu0,
                                             Bh + 0 * 49152, Bh + 1 * 49152,
                                             Bias + 0 * 128, Bias + 1 * 128,
                                             xp1, xu1);
    agg_ll2<<<AGG_BLOCKS, 256>>>(head, ent, xu1, xp1, aggAll);
    gemm_dual<false><<<GP + GU, 256, GSMEM>>>(aVP, aLP, xp1, aVU, aLU, xu1,
                                              Bh + 2 * 49152, Bh + 3 * 49152,
                                              Bias + 2 * 128, Bias + 3 * 128,
                                              outP, outU);
}

// round 17
// speedup vs baseline: 1.0299x; 1.0299x over previous
#include <cuda_runtime.h>
#include <cuda_fp16.h>
#include <cstdint>

#define NU 100000
#define NP 200000
#define H  128
#define EV 500000
#define EL 150000
#define NALL (2*NP + 2*NU)        // 600000
#define NE   (2*(EV + EL))        // 1300000 linked-list entries
#define GP 1563                   // ceil(NP/128)
#define GU 782                    // ceil(NU/128)

// ---------------- scratch layout (4-byte float units) ----------------
#define OFF_AGG 0LL               // agg slots contiguous: [VP|LP|VU|LU] x 128 fp16
#define OFF_XU0 38400000LL        // emb_u fp16
#define OFF_XP0 44800000LL        // emb_p fp16
#define OFF_XU1 57600000LL
#define OFF_XP1 64000000LL
#define OFF_INT 76800000LL
#define OFF_BH  80600000LL        // 4*49152 fp16
#define OFF_BIAS 80698304LL
#define SCRATCH_FLOATS 80700000LL

// int offsets inside int region (3.8M ints available)
#define I_HEAD 0                  // NALL heads
#define I_ENT  600064             // int2 x NE = 2.6M ints

__device__ __align__(1024) float g_scratch[SCRATCH_FLOATS];

// ---------------- PTX helpers (base-target safe, sm_80-class) ----------------
__device__ __forceinline__ uint32_t smem_u32(const void* p) {
    uint32_t a;
    asm("{ .reg .u64 t; cvta.to.shared.u64 t, %1; cvt.u32.u64 %0, t; }" : "=r"(a) : "l"(p));
    return a;
}
__device__ __forceinline__ void ldsm_x4(uint32_t& r0, uint32_t& r1, uint32_t& r2, uint32_t& r3,
                                        uint32_t addr) {
    asm volatile("ldmatrix.sync.aligned.m8n8.x4.shared.b16 {%0,%1,%2,%3}, [%4];"
                 : "=r"(r0), "=r"(r1), "=r"(r2), "=r"(r3) : "r"(addr));
}
__device__ __forceinline__ void mma_f16(float* d, const uint32_t* a, const uint32_t* b) {
    asm volatile("mma.sync.aligned.m16n8k16.row.col.f32.f16.f16.f32 "
                 "{%0,%1,%2,%3}, {%4,%5,%6,%7}, {%8,%9}, {%0,%1,%2,%3};"
                 : "+f"(d[0]), "+f"(d[1]), "+f"(d[2]), "+f"(d[3])
                 : "r"(a[0]), "r"(a[1]), "r"(a[2]), "r"(a[3]), "r"(b[0]), "r"(b[1]));
}
__device__ __forceinline__ void cp16(uint32_t dst, const void* src) {
    asm volatile("cp.async.cg.shared.global [%0], [%1], 16;"
                 :: "r"(dst), "l"(src) : "memory");
}
__device__ __forceinline__ void cp16z(uint32_t dst, const void* src, int sz) {
    asm volatile("cp.async.cg.shared.global [%0], [%1], 16, %2;"
                 :: "r"(dst), "l"(src), "r"(sz) : "memory");
}
#define CP_COMMIT() asm volatile("cp.async.commit_group;" ::: "memory")
#define CP_WAIT1()  asm volatile("cp.async.wait_group 1;" ::: "memory")
#define CP_WAIT0()  asm volatile("cp.async.wait_group 0;" ::: "memory")

// ---------------- prep: B fp16 + bias, emb cvt, head init ----------------
#define CVT_GROUPS ((NU + NP) * 16)
#define CVT_BLOCKS ((CVT_GROUPS + 255) / 256)  // 18750
#define HEAD_BLOCKS ((NALL + 1023) / 1024)     // 586 (4 ints/thread)
#define PREP_GRID (768 + CVT_BLOCKS + HEAD_BLOCKS)
__global__ void k_prep(const float* __restrict__ Wl, const float* __restrict__ bl,
                       const float* __restrict__ Wr,
                       const float* __restrict__ eu, const float* __restrict__ ep,
                       __half* __restrict__ Bh, float* __restrict__ Bias,
                       __half* __restrict__ xu16, __half* __restrict__ xp16,
                       int* __restrict__ head) {
    int b = blockIdx.x;
    if (b < 768) {
        int t = b / 192;
        int idx = (b % 192) * 256 + threadIdx.x;
        int layer = t >> 1, isU = t & 1;
        int rV = isU ? 1 : 0, rL = rV + 2;
        int n = idx / 384, k = idx % 384;
        const float* WlV = Wl + (size_t)((layer * 4 + rV) * 128) * 128;
        const float* WlL = Wl + (size_t)((layer * 4 + rL) * 128) * 128;
        const float* WrV = Wr + (size_t)((layer * 4 + rV) * 128) * 128;
        const float* WrL = Wr + (size_t)((layer * 4 + rL) * 128) * 128;
        float v;
        if (k < 128)      v = WlV[n * 128 + k];
        else if (k < 256) v = WlL[n * 128 + (k - 128)];
        else              v = WrV[n * 128 + (k - 256)] + WrL[n * 128 + (k - 256)];
        Bh[(size_t)t * 49152 + idx] = __float2half_rn(v);
        if (idx < 128)
            Bias[t * 128 + idx] = bl[(layer * 4 + rV) * 128 + idx] + bl[(layer * 4 + rL) * 128 + idx];
    } else if (b < 768 + CVT_BLOCKS) {
        long i = (long)(b - 768) * 256 + threadIdx.x;
        if (i >= CVT_GROUPS) return;
        const float* src; __half* dst; long j;
        if (i < (long)NU * 16) { src = eu; dst = xu16; j = i; }
        else                   { src = ep; dst = xp16; j = i - (long)NU * 16; }
        float4 a = __ldg(reinterpret_cast<const float4*>(src) + j * 2);
        float4 c = __ldg(reinterpret_cast<const float4*>(src) + j * 2 + 1);
        __half2 h0 = __floats2half2_rn(a.x, a.y);
        __half2 h1 = __floats2half2_rn(a.z, a.w);
        __half2 h2 = __floats2half2_rn(c.x, c.y);
        __half2 h3 = __floats2half2_rn(c.z, c.w);
        uint4 o;
        o.x = *reinterpret_cast<uint32_t*>(&h0);
        o.y = *reinterpret_cast<uint32_t*>(&h1);
        o.z = *reinterpret_cast<uint32_t*>(&h2);
        o.w = *reinterpret_cast<uint32_t*>(&h3);
        reinterpret_cast<uint4*>(dst)[j] = o;
    } else {
        long i = (long)(b - 768 - CVT_BLOCKS) * 1024 + threadIdx.x * 4;
        if (i + 3 < NALL)
            *reinterpret_cast<int4*>(head + i) = make_int4(-1, -1, -1, -1);
        else
            for (long q = i; q < NALL; ++q) head[q] = -1;
    }
}

// ---------------- single-pass linked-list CSR build ----------------
__global__ void k_scatter_ll(const int* __restrict__ vs, const int* __restrict__ vd,
                             const int* __restrict__ ls, const int* __restrict__ ld,
                             int* __restrict__ head, int2* __restrict__ ent) {
    int i = blockIdx.x * blockDim.x + threadIdx.x;
    if (i < EV) {
        int s = vs[i], d = vd[i];
        int e0 = i;
        int p0 = atomicExch(&head[d], e0);
        ent[e0] = make_int2(s, p0);
        int e1 = EV + i;
        int p1 = atomicExch(&head[2 * NP + s], e1);
        ent[e1] = make_int2(d, p1);
    }
    if (i < EL) {
        int s = ls[i], d = ld[i];
        int e2 = 2 * EV + i;
        int p2 = atomicExch(&head[NP + d], e2);
        ent[e2] = make_int2(s, p2);
        int e3 = 2 * EV + EL + i;
        int p3 = atomicExch(&head[2 * NP + NU + s], e3);
        ent[e3] = make_int2(d, p3);
    }
}

// ---------------- linked-list mean aggregation: 4 nodes per warp ----------------
// 8 lanes per node, 2 x uint4 (16 halves) per lane; four independent chains per warp.
__global__ void agg_ll4(const int* __restrict__ head, const int2* __restrict__ ent,
                        const __half* __restrict__ xu, const __half* __restrict__ xp,
                        __half* __restrict__ aggAll) {
    int warpid = (blockIdx.x * blockDim.x + threadIdx.x) >> 5;
    int lane = threadIdx.x & 31;
    int quarter = lane >> 3;         // which node of the four
    int l8 = lane & 7;               // lane within node (16 halves each)
    int w = 4 * warpid + quarter;
    if (w >= NALL) return;
    const __half* X = (w < 2 * NP) ? xu : xp;
    int e = __ldg(head + w);
    float2 s0 = make_float2(0.f, 0.f), s1 = make_float2(0.f, 0.f);
    float2 s2 = make_float2(0.f, 0.f), s3 = make_float2(0.f, 0.f);
    float2 s4 = make_float2(0.f, 0.f), s5 = make_float2(0.f, 0.f);
    float2 s6 = make_float2(0.f, 0.f), s7 = make_float2(0.f, 0.f);
    int deg = 0;
    while (e >= 0) {
        int2 t = __ldg(ent + e);
        const uint4* rp = reinterpret_cast<const uint4*>(X + (size_t)t.x * H) + 2 * l8;
        uint4 v0 = __ldg(rp);
        uint4 v1 = __ldg(rp + 1);
        float2 f;
        f = __half22float2(*reinterpret_cast<__half2*>(&v0.x)); s0.x += f.x; s0.y += f.y;
        f = __half22float2(*reinterpret_cast<__half2*>(&v0.y)); s1.x += f.x; s1.y += f.y;
        f = __half22float2(*reinterpret_cast<__half2*>(&v0.z)); s2.x += f.x; s2.y += f.y;
        f = __half22float2(*reinterpret_cast<__half2*>(&v0.w)); s3.x += f.x; s3.y += f.y;
        f = __half22float2(*reinterpret_cast<__half2*>(&v1.x)); s4.x += f.x; s4.y += f.y;
        f = __half22float2(*reinterpret_cast<__half2*>(&v1.y)); s5.x += f.x; s5.y += f.y;
        f = __half22float2(*reinterpret_cast<__half2*>(&v1.z)); s6.x += f.x; s6.y += f.y;
        f = __half22float2(*reinterpret_cast<__half2*>(&v1.w)); s7.x += f.x; s7.y += f.y;
        ++deg;
        e = t.y;
    }
    float inv = 1.0f / fmaxf((float)deg, 1.0f);
    __half2 h0 = __floats2half2_rn(s0.x * inv, s0.y * inv);
    __half2 h1 = __floats2half2_rn(s1.x * inv, s1.y * inv);
    __half2 h2 = __floats2half2_rn(s2.x * inv, s2.y * inv);
    __half2 h3 = __floats2half2_rn(s3.x * inv, s3.y * inv);
    __half2 h4 = __floats2half2_rn(s4.x * inv, s4.y * inv);
    __half2 h5 = __floats2half2_rn(s5.x * inv, s5.y * inv);
    __half2 h6 = __floats2half2_rn(s6.x * inv, s6.y * inv);
    __half2 h7 = __floats2half2_rn(s7.x * inv, s7.y * inv);
    uint4 o0, o1;
    o0.x = *reinterpret_cast<uint32_t*>(&h0);
    o0.y = *reinterpret_cast<uint32_t*>(&h1);
    o0.z = *reinterpret_cast<uint32_t*>(&h2);
    o0.w = *reinterpret_cast<uint32_t*>(&h3);
    o1.x = *reinterpret_cast<uint32_t*>(&h4);
    o1.y = *reinterpret_cast<uint32_t*>(&h5);
    o1.z = *reinterpret_cast<uint32_t*>(&h6);
    o1.w = *reinterpret_cast<uint32_t*>(&h7);
    uint4* op = reinterpret_cast<uint4*>(aggAll + (size_t)w * H) + 2 * l8;
    op[0] = o0;
    op[1] = o1;
}

// ---------------- merged dual-type GEMM (BM=128), cp.async double-buffered ----------------
#define RSTR 72
#define CHUNKB (128 * RSTR * 2)
#define GSMEM (4 * CHUNKB)            // 73728 B

template <bool OUTH>
__global__ void __launch_bounds__(256, 2)
gemm_dual(const __half* __restrict__ pA0, const __half* __restrict__ pA1,
          const __half* __restrict__ pA2,
          const __half* __restrict__ uA0, const __half* __restrict__ uA1,
          const __half* __restrict__ uA2,
          const __half* __restrict__ BhP, const __half* __restrict__ BhU,
          const float* __restrict__ biasP, const float* __restrict__ biasU,
          void* __restrict__ outPv, void* __restrict__ outUv) {
    extern __shared__ __align__(16) __half sm[];
    const uint32_t sbase = smem_u32(sm);
    const uint32_t uAb[2] = {sbase, sbase + CHUNKB};
    const uint32_t uBb[2] = {sbase + 2 * CHUNKB, sbase + 3 * CHUNKB};

    const bool isP = blockIdx.x < GP;
    const int row0 = (isP ? blockIdx.x : blockIdx.x - GP) << 7;
    const int M = isP ? NP : NU;
    const __half* A0 = isP ? pA0 : uA0;
    const __half* A1 = isP ? pA1 : uA1;
    const __half* A2 = isP ? pA2 : uA2;
    const __half* Bh = isP ? BhP : BhU;
    const float* bias = isP ? biasP : biasU;
    void* outv = isP ? outPv : outUv;

    const int tid = threadIdx.x;
    const int warp = tid >> 5, lane = tid & 31;
    const int wm = warp & 3, wn = warp >> 2;

    float acc[2][8][4];
#pragma unroll
    for (int i = 0; i < 2; ++i)
#pragma unroll
        for (int j = 0; j < 8; ++j)
#pragma unroll
            for (int q = 0; q < 4; ++q) acc[i][j][q] = 0.f;

    const int sr = tid >> 1;
    const int shf = (tid & 1) << 5;
    const uint32_t soffB = (uint32_t)(sr * RSTR + shf) * 2;
    const int arow = row0 + sr;
    const int asz = (arow < M) ? 16 : 0;
    const int arowc = (arow < M) ? arow : row0;

    const int lA_row = lane & 15, lA_k = (lane >> 4) << 3;
    const int lB_row = ((lane >> 4) & 1) * 8 + (lane & 7);
    const int lB_k = ((lane >> 3) & 1) << 3;

    auto stage = [&](int c, int bi) {
        const __half* Asrc = (c < 2) ? A0 : (c < 4) ? A1 : A2;
        const int kb = (c & 1) << 6;
        const __half* ap = Asrc + (size_t)arowc * H + kb + shf;
        const __half* bp = Bh + (size_t)sr * 384 + c * 64 + shf;
#pragma unroll
        for (int q = 0; q < 4; ++q)
            cp16z(uAb[bi] + soffB + q * 16, ap + q * 8, asz);
#pragma unroll
        for (int q = 0; q < 4; ++q)
            cp16(uBb[bi] + soffB + q * 16, bp + q * 8);
    };

    stage(0, 0);
    CP_COMMIT();

#pragma unroll 1
    for (int c = 0; c < 6; ++c) {
        const int bi = c & 1;
        if (c < 5) {
            stage(c + 1, bi ^ 1);
            CP_COMMIT();
            CP_WAIT1();
        } else {
            CP_WAIT0();
        }
        __syncthreads();

#pragma unroll
        for (int ks = 0; ks < 4; ++ks) {
            uint32_t af[2][4];
#pragma unroll
            for (int mt = 0; mt < 2; ++mt) {
                uint32_t eo = ((wm * 32 + mt * 16 + lA_row) * RSTR + ks * 16 + lA_k) * 2;
                ldsm_x4(af[mt][0], af[mt][1], af[mt][2], af[mt][3], uAb[bi] + eo);
            }
            uint32_t bf[4][4];
#pragma unroll
            for (int np = 0; np < 4; ++np) {
                uint32_t eo = ((wn * 64 + np * 16 + lB_row) * RSTR + ks * 16 + lB_k) * 2;
                ldsm_x4(bf[np][0], bf[np][1], bf[np][2], bf[np][3], uBb[bi] + eo);
            }
#pragma unroll
            for (int mt = 0; mt < 2; ++mt)
#pragma unroll
                for (int nt = 0; nt < 8; ++nt)
                    mma_f16(acc[mt][nt], af[mt], &bf[nt >> 1][(nt & 1) << 1]);
        }
        __syncthreads();
    }

    const int lr = lane >> 2;
    const int lc = (lane & 3) << 1;
#pragma unroll
    for (int mt = 0; mt < 2; ++mt) {
        int r0 = row0 + wm * 32 + mt * 16 + lr;
#pragma unroll
        for (int nt = 0; nt < 8; ++nt) {
            int cn = wn * 64 + nt * 8 + lc;
            float b0 = __ldg(bias + cn), b1 = __ldg(bias + cn + 1);
            float* a4 = acc[mt][nt];
            if (OUTH) {
                __half* o16 = (__half*)outv;
                if (r0 < M) {
                    __half2 h = __floats2half2_rn(fmaxf(a4[0] + b0, 0.f), fmaxf(a4[1] + b1, 0.f));
                    *reinterpret_cast<__half2*>(o16 + (size_t)r0 * H + cn) = h;
                }
                if (r0 + 8 < M) {
                    __half2 h = __floats2half2_rn(fmaxf(a4[2] + b0, 0.f), fmaxf(a4[3] + b1, 0.f));
                    *reinterpret_cast<__half2*>(o16 + (size_t)(r0 + 8) * H + cn) = h;
                }
            } else {
                float* o32 = (float*)outv;
                if (r0 < M)
                    *reinterpret_cast<float2*>(o32 + (size_t)r0 * H + cn) =
                        make_float2(a4[0] + b0, a4[1] + b1);
                if (r0 + 8 < M)
                    *reinterpret_cast<float2*>(o32 + (size_t)(r0 + 8) * H + cn) =
                        make_float2(a4[2] + b0, a4[3] + b1);
            }
        }
    }
}

// ---------------- host ----------------
extern "C" void kernel_launch(void* const* d_in, const int* in_sizes, int n_in,
                              void* d_out, int out_size) {
    (void)in_sizes; (void)n_in; (void)out_size;
    const float* emb_u = (const float*)d_in[0];
    const float* emb_p = (const float*)d_in[1];
    const float* W_l   = (const float*)d_in[2];
    const float* b_l   = (const float*)d_in[3];
    const float* W_r   = (const float*)d_in[4];
    const int*   ev_s  = (const int*)d_in[5];
    const int*   ev_d  = (const int*)d_in[6];
    const int*   el_s  = (const int*)d_in[7];
    const int*   el_d  = (const int*)d_in[8];

    float* base = 0;
    cudaGetSymbolAddress((void**)&base, g_scratch);

    __half* aggAll = (__half*)(base + OFF_AGG);
    __half* aVP = aggAll;
    __half* aLP = aggAll + (size_t)NP * H;
    __half* aVU = aggAll + (size_t)2 * NP * H;
    __half* aLU = aggAll + (size_t)(2 * NP + NU) * H;
    __half* xu0  = (__half*)(base + OFF_XU0);
    __half* xp0  = (__half*)(base + OFF_XP0);
    __half* xu1  = (__half*)(base + OFF_XU1);
    __half* xp1  = (__half*)(base + OFF_XP1);
    int*  ip   = (int*)(base + OFF_INT);
    int*  head = ip + I_HEAD;
    int2* ent  = (int2*)(ip + I_ENT);
    __half* Bh = (__half*)(base + OFF_BH);
    float* Bias = base + OFF_BIAS;

    float* outU = (float*)d_out;
    float* outP = outU + (size_t)NU * H;

    cudaFuncSetAttribute(gemm_dual<true>,  cudaFuncAttributeMaxDynamicSharedMemorySize, GSMEM);
    cudaFuncSetAttribute(gemm_dual<false>, cudaFuncAttributeMaxDynamicSharedMemorySize, GSMEM);

    // launches: prep(1), scatter_ll(2), agg(3), gemm<true>(4) <- profiled, agg(5), gemm(6)
    k_prep<<<PREP_GRID, 256>>>(W_l, b_l, W_r, emb_u, emb_p, Bh, Bias, xu0, xp0, head);
    k_scatter_ll<<<(EV + 255) / 256, 256>>>(ev_s, ev_d, el_s, el_d, head, ent);

    const int AGG_BLOCKS = (NALL / 4 + 7) / 8;   // 4 nodes/warp, 8 warps/block

    agg_ll4<<<AGG_BLOCKS, 256>>>(head, ent, xu0, xp0, aggAll);
    gemm_dual<true><<<GP + GU, 256, GSMEM>>>(aVP, aLP, xp0, aVU, aLU, xu0,
                                             Bh + 0 * 49152, Bh + 1 * 49152,
                                             Bias + 0 * 128, Bias + 1 * 128,
                                             xp1, xu1);
    agg_ll4<<<AGG_BLOCKS, 256>>>(head, ent, xu1, xp1, aggAll);
    gemm_dual<false><<<GP + GU, 256, GSMEM>>>(aVP, aLP, xp1, aVU, aLU, xu1,
                                              Bh + 2 * 49152, Bh + 3 * 49152,
                                              Bias + 2 * 128, Bias + 3 * 128,
                                              outP, outU);
}